// round 1
// baseline (speedup 1.0000x reference)
#include <cuda_runtime.h>
#include <math.h>

#define NN 100000
#define CH 128

// Scratch (no device allocation allowed)
__device__ float g_h[(size_t)NN * CH];    // current layer features
__device__ float g_t[(size_t)NN * CH];    // h = prev @ W for conv layers
__device__ float g_agg[(size_t)NN * CH];  // aggregation accumulator
__device__ float g_deg[NN];
__device__ float g_dinv[NN];

// ---------------- degree / norm ----------------
__global__ void k_fill_deg(float* deg, int n) {
    int i = blockIdx.x * blockDim.x + threadIdx.x;
    if (i < n) deg[i] = 1.0f;  // self-loop contributes 1
}

__global__ void k_deg_edges(const int* __restrict__ dst, const float* __restrict__ ew,
                            float* deg, int E) {
    int e = blockIdx.x * blockDim.x + threadIdx.x;
    if (e < E) atomicAdd(&deg[dst[e]], ew[e]);
}

__global__ void k_dinv(const float* __restrict__ deg, float* dinv, int n) {
    int i = blockIdx.x * blockDim.x + threadIdx.x;
    if (i < n) dinv[i] = rsqrtf(deg[i]);
}

// ---------------- GEMM: [M,K] @ [K,128] ----------------
// EPI==0: out = relu(acc + bias)
// EPI==1: out = acc (raw h), agg = dinv[row]^2 * acc (self-loop init)
template <int K, int EPI>
__global__ __launch_bounds__(256) void k_gemm(
    const float* __restrict__ A, const float* __restrict__ W,
    const float* __restrict__ bias, const float* __restrict__ dinv,
    float* __restrict__ out, float* __restrict__ agg, int M)
{
    __shared__ float As[16][64];
    __shared__ float Ws[16][128];

    const int tid = threadIdx.x;
    const int tx = tid & 31;   // col group: cols tx*4 .. tx*4+3
    const int ty = tid >> 5;   // row group: rows ty*8 .. ty*8+7
    const int row0 = blockIdx.x * 64;

    float acc[8][4];
#pragma unroll
    for (int i = 0; i < 8; i++)
#pragma unroll
        for (int j = 0; j < 4; j++) acc[i][j] = 0.0f;

    const int lr = tid >> 2;           // 0..63 : A load row
    const int lk = (tid & 3) * 4;      // 0,4,8,12 : A load k-offset
    const int wk = tid >> 4;           // 0..15 : W load k
    const int wc = (tid & 15) * 8;     // 0..120 : W load col

    for (int k0 = 0; k0 < K; k0 += 16) {
        float4 av = make_float4(0.f, 0.f, 0.f, 0.f);
        int gr = row0 + lr;
        if (gr < M) av = *(const float4*)&A[(size_t)gr * K + k0 + lk];
        As[lk + 0][lr] = av.x;
        As[lk + 1][lr] = av.y;
        As[lk + 2][lr] = av.z;
        As[lk + 3][lr] = av.w;

        *(float4*)&Ws[wk][wc]     = *(const float4*)&W[(size_t)(k0 + wk) * 128 + wc];
        *(float4*)&Ws[wk][wc + 4] = *(const float4*)&W[(size_t)(k0 + wk) * 128 + wc + 4];
        __syncthreads();

#pragma unroll
        for (int kk = 0; kk < 16; kk++) {
            float4 b = *(float4*)&Ws[kk][tx * 4];
            float4 a0 = *(float4*)&As[kk][ty * 8];
            float4 a1 = *(float4*)&As[kk][ty * 8 + 4];
            float ar[8] = {a0.x, a0.y, a0.z, a0.w, a1.x, a1.y, a1.z, a1.w};
#pragma unroll
            for (int i = 0; i < 8; i++) {
                acc[i][0] += ar[i] * b.x;
                acc[i][1] += ar[i] * b.y;
                acc[i][2] += ar[i] * b.z;
                acc[i][3] += ar[i] * b.w;
            }
        }
        __syncthreads();
    }

    const int col = tx * 4;
#pragma unroll
    for (int i = 0; i < 8; i++) {
        int r = row0 + ty * 8 + i;
        if (r >= M) break;
        float4 v = make_float4(acc[i][0], acc[i][1], acc[i][2], acc[i][3]);
        if (EPI == 0) {
            float4 bv = *(const float4*)&bias[col];
            v.x = fmaxf(v.x + bv.x, 0.f);
            v.y = fmaxf(v.y + bv.y, 0.f);
            v.z = fmaxf(v.z + bv.z, 0.f);
            v.w = fmaxf(v.w + bv.w, 0.f);
            *(float4*)&out[(size_t)r * 128 + col] = v;
        } else {
            *(float4*)&out[(size_t)r * 128 + col] = v;
            float di = dinv[r];
            float s = di * di;
            float4 a = make_float4(v.x * s, v.y * s, v.z * s, v.w * s);
            *(float4*)&agg[(size_t)r * 128 + col] = a;
        }
    }
}

// ---------------- edge messages: agg[dst] += dinv[src]*ew*dinv[dst] * h[src] ----------------
__global__ __launch_bounds__(256) void k_edge(
    const int* __restrict__ src, const int* __restrict__ dst,
    const float* __restrict__ ew, const float* __restrict__ dinv,
    const float* __restrict__ h, float* __restrict__ agg, int E)
{
    int w = (blockIdx.x * blockDim.x + threadIdx.x) >> 5;
    if (w >= E) return;
    int lane = threadIdx.x & 31;
    int s = __ldg(src + w);
    int d = __ldg(dst + w);
    float c = __ldg(dinv + s) * __ldg(ew + w) * __ldg(dinv + d);
    float4 hv = *(const float4*)(h + (size_t)s * CH + lane * 4);
    float* ap = agg + (size_t)d * CH + lane * 4;
    atomicAdd(ap + 0, c * hv.x);
    atomicAdd(ap + 1, c * hv.y);
    atomicAdd(ap + 2, c * hv.z);
    atomicAdd(ap + 3, c * hv.w);
}

// ---------------- finalize: out = relu(agg + b) ----------------
__global__ void k_finalize(const float* __restrict__ agg, const float* __restrict__ b,
                           float* __restrict__ out, int n4)
{
    int i = blockIdx.x * blockDim.x + threadIdx.x;
    if (i >= n4) return;
    float4 v = ((const float4*)agg)[i];
    int col = (i & 31) * 4;
    float4 bv = *(const float4*)(b + col);
    v.x = fmaxf(v.x + bv.x, 0.f);
    v.y = fmaxf(v.y + bv.y, 0.f);
    v.z = fmaxf(v.z + bv.z, 0.f);
    v.w = fmaxf(v.w + bv.w, 0.f);
    ((float4*)out)[i] = v;
}

// ---------------- logits + softmax: out = softmax(h @ Wl2 + bl2), N=32 ----------------
__global__ __launch_bounds__(256) void k_logits_softmax(
    const float* __restrict__ h, const float* __restrict__ Wl2,
    const float* __restrict__ bl2, float* __restrict__ out, int M)
{
    __shared__ float hs[8][128];
    int tid = threadIdx.x;
    int warp = tid >> 5;
    int lane = tid & 31;
    int row0 = blockIdx.x * 8;

    // cooperative load: 8 rows x 128 = 256 float4, one per thread
    {
        int rloc = tid >> 5;          // 0..7
        int cloc = (tid & 31) * 4;    // 0..124
        int r = row0 + rloc;
        float4 v = make_float4(0.f, 0.f, 0.f, 0.f);
        if (r < M) v = *(const float4*)&h[(size_t)r * 128 + cloc];
        *(float4*)&hs[rloc][cloc] = v;
    }
    __syncthreads();

    int r = row0 + warp;
    if (r >= M) return;

    float acc = bl2[lane];
#pragma unroll
    for (int k = 0; k < 128; k++) {
        acc += hs[warp][k] * __ldg(&Wl2[(size_t)k * 32 + lane]);
    }

    // softmax over 32 lanes
    float m = acc;
#pragma unroll
    for (int o = 16; o >= 1; o >>= 1) m = fmaxf(m, __shfl_xor_sync(0xFFFFFFFFu, m, o));
    float e = __expf(acc - m);
    float s = e;
#pragma unroll
    for (int o = 16; o >= 1; o >>= 1) s += __shfl_xor_sync(0xFFFFFFFFu, s, o);
    out[(size_t)r * 32 + lane] = e / s;
}

// ---------------- launch ----------------
extern "C" void kernel_launch(void* const* d_in, const int* in_sizes, int n_in,
                              void* d_out, int out_size)
{
    const float* x   = (const float*)d_in[0];
    const int*   ei  = (const int*)d_in[1];
    const float* ew  = (const float*)d_in[2];
    const float* Wp  = (const float*)d_in[3];
    const float* bp  = (const float*)d_in[4];
    const float* W1  = (const float*)d_in[5];
    const float* b1  = (const float*)d_in[6];
    const float* W2  = (const float*)d_in[7];
    const float* b2  = (const float*)d_in[8];
    const float* Wl1 = (const float*)d_in[9];
    const float* bl1 = (const float*)d_in[10];
    const float* Wl2 = (const float*)d_in[11];
    const float* bl2 = (const float*)d_in[12];
    float* out = (float*)d_out;

    const int M = in_sizes[0] / 256;       // 100000
    const int E = in_sizes[1] / 2;         // 1600000
    const int* src = ei;
    const int* dst = ei + E;

    float *p_h, *p_t, *p_agg, *p_deg, *p_dinv;
    cudaGetSymbolAddress((void**)&p_h, g_h);
    cudaGetSymbolAddress((void**)&p_t, g_t);
    cudaGetSymbolAddress((void**)&p_agg, g_agg);
    cudaGetSymbolAddress((void**)&p_deg, g_deg);
    cudaGetSymbolAddress((void**)&p_dinv, g_dinv);

    const int gemm_blocks = (M + 63) / 64;
    const int n4 = M * 32;  // M*128/4 float4s

    // degrees + normalization coefficients
    k_fill_deg<<<(M + 255) / 256, 256>>>(p_deg, M);
    k_deg_edges<<<(E + 255) / 256, 256>>>(dst, ew, p_deg, E);
    k_dinv<<<(M + 255) / 256, 256>>>(p_deg, p_dinv, M);

    // h0 = relu(x @ Wp + bp)
    k_gemm<256, 0><<<gemm_blocks, 256>>>(x, Wp, bp, nullptr, p_h, nullptr, M);

    // conv1: t = h0 @ W1; agg = dinv^2 * t; scatter; h = relu(agg + b1)
    k_gemm<128, 1><<<gemm_blocks, 256>>>(p_h, W1, nullptr, p_dinv, p_t, p_agg, M);
    k_edge<<<(E + 7) / 8, 256>>>(src, dst, ew, p_dinv, p_t, p_agg, E);
    k_finalize<<<(n4 + 255) / 256, 256>>>(p_agg, b1, p_h, n4);

    // conv2
    k_gemm<128, 1><<<gemm_blocks, 256>>>(p_h, W2, nullptr, p_dinv, p_t, p_agg, M);
    k_edge<<<(E + 7) / 8, 256>>>(src, dst, ew, p_dinv, p_t, p_agg, E);
    k_finalize<<<(n4 + 255) / 256, 256>>>(p_agg, b2, p_h, n4);

    // h = relu(h @ Wl1 + bl1)
    k_gemm<128, 0><<<gemm_blocks, 256>>>(p_h, Wl1, bl1, nullptr, p_t, nullptr, M);

    // softmax(h @ Wl2 + bl2)
    k_logits_softmax<<<(M + 7) / 8, 256>>>(p_t, Wl2, bl2, out, M);
}

// round 2
// speedup vs baseline: 1.7901x; 1.7901x over previous
#include <cuda_runtime.h>
#include <math.h>

#define NN 100000
#define EE 1600000
#define CH 128

// Scratch (no device allocation allowed)
__device__ float g_h[(size_t)NN * CH];
__device__ float g_t[(size_t)NN * CH];
__device__ float g_deg[NN];
__device__ float g_dinv[NN];
__device__ int   g_cnt[NN];
__device__ int   g_off[NN + 1];
__device__ int   g_cur[NN];
__device__ int   g_esrc[EE];
__device__ float g_ecoef[EE];

// ---------------- init: deg=1 (self loop), cnt=0 ----------------
__global__ void k_init(float* deg, int* cnt, int n) {
    int i = blockIdx.x * blockDim.x + threadIdx.x;
    if (i < n) { deg[i] = 1.0f; cnt[i] = 0; }
}

// ---------------- per-edge: deg[dst]+=ew, cnt[dst]+=1 ----------------
__global__ void k_edge_deg(const int* __restrict__ dst, const float* __restrict__ ew,
                           float* deg, int* cnt, int E) {
    int e = blockIdx.x * blockDim.x + threadIdx.x;
    if (e < E) {
        int d = dst[e];
        atomicAdd(&deg[d], ew[e]);
        atomicAdd(&cnt[d], 1);
    }
}

__global__ void k_dinv(const float* __restrict__ deg, float* dinv, int n) {
    int i = blockIdx.x * blockDim.x + threadIdx.x;
    if (i < n) dinv[i] = rsqrtf(deg[i]);
}

// ---------------- single-block exclusive scan of cnt -> off, cur ----------------
__global__ __launch_bounds__(1024) void k_scan(const int* __restrict__ cnt,
                                               int* off, int* cur, int n) {
    __shared__ int ssum[1024];
    int tid = threadIdx.x;
    int per = (n + 1023) / 1024;
    int beg = tid * per;
    int end = beg + per; if (end > n) end = n;
    if (beg > n) beg = n;

    int s = 0;
    for (int i = beg; i < end; i++) s += cnt[i];
    ssum[tid] = s;
    __syncthreads();

    // Hillis-Steele inclusive scan
    for (int d = 1; d < 1024; d <<= 1) {
        int add = (tid >= d) ? ssum[tid - d] : 0;
        __syncthreads();
        ssum[tid] += add;
        __syncthreads();
    }
    int run = ssum[tid] - s;  // exclusive prefix for this thread's chunk
    for (int i = beg; i < end; i++) {
        off[i] = run; cur[i] = run;
        run += cnt[i];
    }
    if (tid == 1023) off[n] = ssum[1023];
}

// ---------------- scatter edges into CSR with precomputed coefficients ----------------
__global__ void k_scatter(const int* __restrict__ src, const int* __restrict__ dst,
                          const float* __restrict__ ew, const float* __restrict__ dinv,
                          int* cur, int* esrc, float* ecoef, int E) {
    int e = blockIdx.x * blockDim.x + threadIdx.x;
    if (e >= E) return;
    int s = src[e];
    int d = dst[e];
    int pos = atomicAdd(&cur[d], 1);
    esrc[pos]  = s;
    ecoef[pos] = __ldg(dinv + s) * ew[e] * __ldg(dinv + d);
}

// ---------------- GEMM: [M,K] @ [K,128] ----------------
// EPI==0: out = relu(acc + bias);  EPI==1: out = acc
template <int K, int EPI>
__global__ __launch_bounds__(256) void k_gemm(
    const float* __restrict__ A, const float* __restrict__ W,
    const float* __restrict__ bias, float* __restrict__ out, int M)
{
    __shared__ float As[16][64];
    __shared__ float Ws[16][128];

    const int tid = threadIdx.x;
    const int tx = tid & 31;
    const int ty = tid >> 5;
    const int row0 = blockIdx.x * 64;

    float acc[8][4];
#pragma unroll
    for (int i = 0; i < 8; i++)
#pragma unroll
        for (int j = 0; j < 4; j++) acc[i][j] = 0.0f;

    const int lr = tid >> 2;
    const int lk = (tid & 3) * 4;
    const int wk = tid >> 4;
    const int wc = (tid & 15) * 8;

    for (int k0 = 0; k0 < K; k0 += 16) {
        float4 av = make_float4(0.f, 0.f, 0.f, 0.f);
        int gr = row0 + lr;
        if (gr < M) av = *(const float4*)&A[(size_t)gr * K + k0 + lk];
        As[lk + 0][lr] = av.x;
        As[lk + 1][lr] = av.y;
        As[lk + 2][lr] = av.z;
        As[lk + 3][lr] = av.w;

        *(float4*)&Ws[wk][wc]     = *(const float4*)&W[(size_t)(k0 + wk) * 128 + wc];
        *(float4*)&Ws[wk][wc + 4] = *(const float4*)&W[(size_t)(k0 + wk) * 128 + wc + 4];
        __syncthreads();

#pragma unroll
        for (int kk = 0; kk < 16; kk++) {
            float4 b = *(float4*)&Ws[kk][tx * 4];
            float4 a0 = *(float4*)&As[kk][ty * 8];
            float4 a1 = *(float4*)&As[kk][ty * 8 + 4];
            float ar[8] = {a0.x, a0.y, a0.z, a0.w, a1.x, a1.y, a1.z, a1.w};
#pragma unroll
            for (int i = 0; i < 8; i++) {
                acc[i][0] += ar[i] * b.x;
                acc[i][1] += ar[i] * b.y;
                acc[i][2] += ar[i] * b.z;
                acc[i][3] += ar[i] * b.w;
            }
        }
        __syncthreads();
    }

    const int col = tx * 4;
#pragma unroll
    for (int i = 0; i < 8; i++) {
        int r = row0 + ty * 8 + i;
        if (r >= M) break;
        float4 v = make_float4(acc[i][0], acc[i][1], acc[i][2], acc[i][3]);
        if (EPI == 0) {
            float4 bv = *(const float4*)&bias[col];
            v.x = fmaxf(v.x + bv.x, 0.f);
            v.y = fmaxf(v.y + bv.y, 0.f);
            v.z = fmaxf(v.z + bv.z, 0.f);
            v.w = fmaxf(v.w + bv.w, 0.f);
        }
        *(float4*)&out[(size_t)r * 128 + col] = v;
    }
}

// ---------------- gather aggregation: one warp per node ----------------
// out[n] = relu( dinv[n]^2 * t[n] + sum_e coef[e]*t[esrc[e]] + bias )
__global__ __launch_bounds__(256) void k_agg(
    const int* __restrict__ off, const int* __restrict__ esrc,
    const float* __restrict__ ecoef, const float* __restrict__ t,
    const float* __restrict__ dinv, const float* __restrict__ bias,
    float* __restrict__ out, int n)
{
    int w = (blockIdx.x * blockDim.x + threadIdx.x) >> 5;
    if (w >= n) return;
    int lane = threadIdx.x & 31;

    const float4* tp = (const float4*)t;
    int beg = __ldg(off + w);
    int end = __ldg(off + w + 1);

    float di = __ldg(dinv + w);
    float s = di * di;
    float4 acc = tp[(size_t)w * 32 + lane];
    acc.x *= s; acc.y *= s; acc.z *= s; acc.w *= s;

    int e = beg;
    for (; e + 1 < end; e += 2) {
        int s0 = __ldg(esrc + e);
        int s1 = __ldg(esrc + e + 1);
        float c0 = __ldg(ecoef + e);
        float c1 = __ldg(ecoef + e + 1);
        float4 h0 = tp[(size_t)s0 * 32 + lane];
        float4 h1 = tp[(size_t)s1 * 32 + lane];
        acc.x += c0 * h0.x + c1 * h1.x;
        acc.y += c0 * h0.y + c1 * h1.y;
        acc.z += c0 * h0.z + c1 * h1.z;
        acc.w += c0 * h0.w + c1 * h1.w;
    }
    if (e < end) {
        int s0 = __ldg(esrc + e);
        float c0 = __ldg(ecoef + e);
        float4 h0 = tp[(size_t)s0 * 32 + lane];
        acc.x += c0 * h0.x;
        acc.y += c0 * h0.y;
        acc.z += c0 * h0.z;
        acc.w += c0 * h0.w;
    }

    float4 bv = *(const float4*)&bias[lane * 4];
    acc.x = fmaxf(acc.x + bv.x, 0.f);
    acc.y = fmaxf(acc.y + bv.y, 0.f);
    acc.z = fmaxf(acc.z + bv.z, 0.f);
    acc.w = fmaxf(acc.w + bv.w, 0.f);
    ((float4*)out)[(size_t)w * 32 + lane] = acc;
}

// ---------------- logits + softmax ----------------
__global__ __launch_bounds__(256) void k_logits_softmax(
    const float* __restrict__ h, const float* __restrict__ Wl2,
    const float* __restrict__ bl2, float* __restrict__ out, int M)
{
    __shared__ float hs[8][128];
    int tid = threadIdx.x;
    int warp = tid >> 5;
    int lane = tid & 31;
    int row0 = blockIdx.x * 8;

    {
        int rloc = tid >> 5;
        int cloc = (tid & 31) * 4;
        int r = row0 + rloc;
        float4 v = make_float4(0.f, 0.f, 0.f, 0.f);
        if (r < M) v = *(const float4*)&h[(size_t)r * 128 + cloc];
        *(float4*)&hs[rloc][cloc] = v;
    }
    __syncthreads();

    int r = row0 + warp;
    if (r >= M) return;

    float acc = bl2[lane];
#pragma unroll
    for (int k = 0; k < 128; k++) {
        acc += hs[warp][k] * __ldg(&Wl2[(size_t)k * 32 + lane]);
    }

    float m = acc;
#pragma unroll
    for (int o = 16; o >= 1; o >>= 1) m = fmaxf(m, __shfl_xor_sync(0xFFFFFFFFu, m, o));
    float e = __expf(acc - m);
    float s = e;
#pragma unroll
    for (int o = 16; o >= 1; o >>= 1) s += __shfl_xor_sync(0xFFFFFFFFu, s, o);
    out[(size_t)r * 32 + lane] = e / s;
}

// ---------------- launch ----------------
extern "C" void kernel_launch(void* const* d_in, const int* in_sizes, int n_in,
                              void* d_out, int out_size)
{
    const float* x   = (const float*)d_in[0];
    const int*   ei  = (const int*)d_in[1];
    const float* ew  = (const float*)d_in[2];
    const float* Wp  = (const float*)d_in[3];
    const float* bp  = (const float*)d_in[4];
    const float* W1  = (const float*)d_in[5];
    const float* b1  = (const float*)d_in[6];
    const float* W2  = (const float*)d_in[7];
    const float* b2  = (const float*)d_in[8];
    const float* Wl1 = (const float*)d_in[9];
    const float* bl1 = (const float*)d_in[10];
    const float* Wl2 = (const float*)d_in[11];
    const float* bl2 = (const float*)d_in[12];
    float* out = (float*)d_out;

    const int M = in_sizes[0] / 256;   // 100000
    const int E = in_sizes[1] / 2;     // 1600000
    const int* src = ei;
    const int* dst = ei + E;

    float *p_h, *p_t, *p_deg, *p_dinv, *p_ecoef;
    int *p_cnt, *p_off, *p_cur, *p_esrc;
    cudaGetSymbolAddress((void**)&p_h, g_h);
    cudaGetSymbolAddress((void**)&p_t, g_t);
    cudaGetSymbolAddress((void**)&p_deg, g_deg);
    cudaGetSymbolAddress((void**)&p_dinv, g_dinv);
    cudaGetSymbolAddress((void**)&p_cnt, g_cnt);
    cudaGetSymbolAddress((void**)&p_off, g_off);
    cudaGetSymbolAddress((void**)&p_cur, g_cur);
    cudaGetSymbolAddress((void**)&p_esrc, g_esrc);
    cudaGetSymbolAddress((void**)&p_ecoef, g_ecoef);

    const int gemm_blocks = (M + 63) / 64;
    const int agg_blocks  = (M + 7) / 8;   // 8 warps/block, 1 warp/node

    // CSR build + normalization (reused by both conv layers)
    k_init<<<(M + 255) / 256, 256>>>(p_deg, p_cnt, M);
    k_edge_deg<<<(E + 255) / 256, 256>>>(dst, ew, p_deg, p_cnt, E);
    k_dinv<<<(M + 255) / 256, 256>>>(p_deg, p_dinv, M);
    k_scan<<<1, 1024>>>(p_cnt, p_off, p_cur, M);
    k_scatter<<<(E + 255) / 256, 256>>>(src, dst, ew, p_dinv, p_cur, p_esrc, p_ecoef, E);

    // h0 = relu(x @ Wp + bp)
    k_gemm<256, 0><<<gemm_blocks, 256>>>(x, Wp, bp, p_h, M);

    // conv1: t = h0 @ W1; h = relu(aggregate(t) + b1)
    k_gemm<128, 1><<<gemm_blocks, 256>>>(p_h, W1, nullptr, p_t, M);
    k_agg<<<agg_blocks, 256>>>(p_off, p_esrc, p_ecoef, p_t, p_dinv, b1, p_h, M);

    // conv2
    k_gemm<128, 1><<<gemm_blocks, 256>>>(p_h, W2, nullptr, p_t, M);
    k_agg<<<agg_blocks, 256>>>(p_off, p_esrc, p_ecoef, p_t, p_dinv, b2, p_h, M);

    // h = relu(h @ Wl1 + bl1)
    k_gemm<128, 0><<<gemm_blocks, 256>>>(p_h, Wl1, bl1, p_t, M);

    // softmax(h @ Wl2 + bl2)
    k_logits_softmax<<<(M + 7) / 8, 256>>>(p_t, Wl2, bl2, out, M);
}

// round 3
// speedup vs baseline: 1.9581x; 1.0938x over previous
#include <cuda_runtime.h>
#include <math.h>

#define NN 100000
#define EE 1600000
#define CH 128
#define SCAN_CHUNK 256
#define SCAN_BLOCKS ((NN + SCAN_CHUNK - 1) / SCAN_CHUNK)

// Scratch (no device allocation allowed)
__device__ float g_h[(size_t)NN * CH];
__device__ float g_t[(size_t)NN * CH];
__device__ float g_deg[NN];
__device__ float g_dinv[NN];
__device__ int   g_cnt[NN];
__device__ int   g_off[NN + 1];
__device__ int   g_cur[NN];
__device__ int   g_esrc[EE];
__device__ float g_ecoef[EE];
__device__ int   g_part[512];

// ---------------- init: deg=1 (self loop), cnt=0 ----------------
__global__ void k_init(float* deg, int* cnt, int n) {
    int i = blockIdx.x * blockDim.x + threadIdx.x;
    if (i < n) { deg[i] = 1.0f; cnt[i] = 0; }
}

// ---------------- per-edge: deg[dst]+=ew, cnt[dst]+=1 ----------------
__global__ void k_edge_deg(const int* __restrict__ dst, const float* __restrict__ ew,
                           float* deg, int* cnt, int E) {
    int e = blockIdx.x * blockDim.x + threadIdx.x;
    if (e < E) {
        int d = dst[e];
        atomicAdd(&deg[d], ew[e]);
        atomicAdd(&cnt[d], 1);
    }
}

__global__ void k_dinv(const float* __restrict__ deg, float* dinv, int n) {
    int i = blockIdx.x * blockDim.x + threadIdx.x;
    if (i < n) dinv[i] = rsqrtf(deg[i]);
}

// ---------------- parallel scan, phase 1: per-block sums ----------------
__global__ __launch_bounds__(SCAN_CHUNK) void k_scan1(const int* __restrict__ cnt,
                                                      int* part, int n) {
    __shared__ int ws[8];
    int i = blockIdx.x * SCAN_CHUNK + threadIdx.x;
    int v = (i < n) ? cnt[i] : 0;
#pragma unroll
    for (int o = 16; o >= 1; o >>= 1) v += __shfl_xor_sync(0xFFFFFFFFu, v, o);
    if ((threadIdx.x & 31) == 0) ws[threadIdx.x >> 5] = v;
    __syncthreads();
    if (threadIdx.x == 0) {
        int s = 0;
#pragma unroll
        for (int w = 0; w < 8; w++) s += ws[w];
        part[blockIdx.x] = s;
    }
}

// ---------------- phase 2: single-block exclusive scan of partials ----------------
__global__ __launch_bounds__(512) void k_scan2(int* part, int nb) {
    __shared__ int s[512];
    int tid = threadIdx.x;
    int v = (tid < nb) ? part[tid] : 0;
    s[tid] = v;
    __syncthreads();
#pragma unroll
    for (int d = 1; d < 512; d <<= 1) {
        int add = (tid >= d) ? s[tid - d] : 0;
        __syncthreads();
        s[tid] += add;
        __syncthreads();
    }
    if (tid < nb) part[tid] = s[tid] - v;  // exclusive
}

// ---------------- phase 3: per-block exclusive rescan + base ----------------
__global__ __launch_bounds__(SCAN_CHUNK) void k_scan3(const int* __restrict__ cnt,
                                                      const int* __restrict__ part,
                                                      int* off, int* cur, int n, int E) {
    __shared__ int ws[8];
    int tid = threadIdx.x;
    int i = blockIdx.x * SCAN_CHUNK + tid;
    int lane = tid & 31;
    int warp = tid >> 5;
    int v = (i < n) ? cnt[i] : 0;
    int x = v;
#pragma unroll
    for (int o = 1; o < 32; o <<= 1) {
        int y = __shfl_up_sync(0xFFFFFFFFu, x, o);
        if (lane >= o) x += y;
    }
    if (lane == 31) ws[warp] = x;
    __syncthreads();
    if (warp == 0 && lane < 8) {
        int y = ws[lane];
        int z = y;
#pragma unroll
        for (int o = 1; o < 8; o <<= 1) {
            int u = __shfl_up_sync(0xFFu, z, o);
            if (lane >= o) z += u;
        }
        ws[lane] = z - y;  // exclusive warp base
    }
    __syncthreads();
    if (i < n) {
        int excl = part[blockIdx.x] + ws[warp] + x - v;
        off[i] = excl;
        cur[i] = excl;
    }
    if (i == n - 1) off[n] = E;
}

// ---------------- scatter edges into CSR with precomputed coefficients ----------------
__global__ void k_scatter(const int* __restrict__ src, const int* __restrict__ dst,
                          const float* __restrict__ ew, const float* __restrict__ dinv,
                          int* cur, int* esrc, float* ecoef, int E) {
    int e = blockIdx.x * blockDim.x + threadIdx.x;
    if (e >= E) return;
    int s = src[e];
    int d = dst[e];
    int pos = atomicAdd(&cur[d], 1);
    esrc[pos]  = s;
    ecoef[pos] = __ldg(dinv + s) * ew[e] * __ldg(dinv + d);
}

// ---------------- GEMM: [M,K] @ [K,128], 128x128 tile, 8x8 micro ----------------
// EPI==0: out = relu(acc + bias);  EPI==1: out = acc
template <int K, int EPI>
__global__ __launch_bounds__(256) void k_gemm(
    const float* __restrict__ A, const float* __restrict__ W,
    const float* __restrict__ bias, float* __restrict__ out, int M)
{
    __shared__ float As[8][128];
    __shared__ float Ws[8][128];

    const int tid = threadIdx.x;
    const int tx = (tid & 15) * 8;   // col 0..120
    const int ty = (tid >> 4) * 8;   // row 0..120
    const int row0 = blockIdx.x * 128;

    float acc[8][8];
#pragma unroll
    for (int i = 0; i < 8; i++)
#pragma unroll
        for (int j = 0; j < 8; j++) acc[i][j] = 0.0f;

    const int ar = tid >> 1;          // 0..127 : A load row
    const int ak = (tid & 1) * 4;     // 0 or 4 : A load k-offset
    const int wr = tid >> 5;          // 0..7   : W load k
    const int wc = (tid & 31) * 4;    // 0..124 : W load col

    for (int k0 = 0; k0 < K; k0 += 8) {
        float4 av = make_float4(0.f, 0.f, 0.f, 0.f);
        int gr = row0 + ar;
        if (gr < M) av = *(const float4*)&A[(size_t)gr * K + k0 + ak];
        As[ak + 0][ar] = av.x;
        As[ak + 1][ar] = av.y;
        As[ak + 2][ar] = av.z;
        As[ak + 3][ar] = av.w;
        *(float4*)&Ws[wr][wc] = *(const float4*)&W[(size_t)(k0 + wr) * 128 + wc];
        __syncthreads();

#pragma unroll
        for (int kk = 0; kk < 8; kk++) {
            float a[8], b[8];
            *(float4*)&a[0] = *(float4*)&As[kk][ty];
            *(float4*)&a[4] = *(float4*)&As[kk][ty + 4];
            *(float4*)&b[0] = *(float4*)&Ws[kk][tx];
            *(float4*)&b[4] = *(float4*)&Ws[kk][tx + 4];
#pragma unroll
            for (int i = 0; i < 8; i++)
#pragma unroll
                for (int j = 0; j < 8; j++)
                    acc[i][j] += a[i] * b[j];
        }
        __syncthreads();
    }

    float bv[8];
    if (EPI == 0) {
        *(float4*)&bv[0] = *(const float4*)&bias[tx];
        *(float4*)&bv[4] = *(const float4*)&bias[tx + 4];
    }
#pragma unroll
    for (int i = 0; i < 8; i++) {
        int r = row0 + ty + i;
        if (r >= M) break;
        float o[8];
#pragma unroll
        for (int j = 0; j < 8; j++) {
            o[j] = acc[i][j];
            if (EPI == 0) o[j] = fmaxf(o[j] + bv[j], 0.f);
        }
        *(float4*)&out[(size_t)r * 128 + tx]     = *(float4*)&o[0];
        *(float4*)&out[(size_t)r * 128 + tx + 4] = *(float4*)&o[4];
    }
}

// ---------------- gather aggregation: one warp per node ----------------
__global__ __launch_bounds__(256) void k_agg(
    const int* __restrict__ off, const int* __restrict__ esrc,
    const float* __restrict__ ecoef, const float* __restrict__ t,
    const float* __restrict__ dinv, const float* __restrict__ bias,
    float* __restrict__ out, int n)
{
    int w = (blockIdx.x * blockDim.x + threadIdx.x) >> 5;
    if (w >= n) return;
    int lane = threadIdx.x & 31;

    const float4* tp = (const float4*)t;
    int beg = __ldg(off + w);
    int end = __ldg(off + w + 1);

    float di = __ldg(dinv + w);
    float s = di * di;
    float4 acc = tp[(size_t)w * 32 + lane];
    acc.x *= s; acc.y *= s; acc.z *= s; acc.w *= s;

    int e = beg;
    for (; e + 1 < end; e += 2) {
        int s0 = __ldg(esrc + e);
        int s1 = __ldg(esrc + e + 1);
        float c0 = __ldg(ecoef + e);
        float c1 = __ldg(ecoef + e + 1);
        float4 h0 = tp[(size_t)s0 * 32 + lane];
        float4 h1 = tp[(size_t)s1 * 32 + lane];
        acc.x += c0 * h0.x + c1 * h1.x;
        acc.y += c0 * h0.y + c1 * h1.y;
        acc.z += c0 * h0.z + c1 * h1.z;
        acc.w += c0 * h0.w + c1 * h1.w;
    }
    if (e < end) {
        int s0 = __ldg(esrc + e);
        float c0 = __ldg(ecoef + e);
        float4 h0 = tp[(size_t)s0 * 32 + lane];
        acc.x += c0 * h0.x;
        acc.y += c0 * h0.y;
        acc.z += c0 * h0.z;
        acc.w += c0 * h0.w;
    }

    float4 bv = *(const float4*)&bias[lane * 4];
    acc.x = fmaxf(acc.x + bv.x, 0.f);
    acc.y = fmaxf(acc.y + bv.y, 0.f);
    acc.z = fmaxf(acc.z + bv.z, 0.f);
    acc.w = fmaxf(acc.w + bv.w, 0.f);
    ((float4*)out)[(size_t)w * 32 + lane] = acc;
}

// ---------------- logits + softmax ----------------
__global__ __launch_bounds__(256) void k_logits_softmax(
    const float* __restrict__ h, const float* __restrict__ Wl2,
    const float* __restrict__ bl2, float* __restrict__ out, int M)
{
    __shared__ float hs[8][128];
    int tid = threadIdx.x;
    int warp = tid >> 5;
    int lane = tid & 31;
    int row0 = blockIdx.x * 8;

    {
        int rloc = tid >> 5;
        int cloc = (tid & 31) * 4;
        int r = row0 + rloc;
        float4 v = make_float4(0.f, 0.f, 0.f, 0.f);
        if (r < M) v = *(const float4*)&h[(size_t)r * 128 + cloc];
        *(float4*)&hs[rloc][cloc] = v;
    }
    __syncthreads();

    int r = row0 + warp;
    if (r >= M) return;

    float acc = bl2[lane];
#pragma unroll
    for (int k = 0; k < 128; k++) {
        acc += hs[warp][k] * __ldg(&Wl2[(size_t)k * 32 + lane]);
    }

    float m = acc;
#pragma unroll
    for (int o = 16; o >= 1; o >>= 1) m = fmaxf(m, __shfl_xor_sync(0xFFFFFFFFu, m, o));
    float e = __expf(acc - m);
    float s = e;
#pragma unroll
    for (int o = 16; o >= 1; o >>= 1) s += __shfl_xor_sync(0xFFFFFFFFu, s, o);
    out[(size_t)r * 32 + lane] = e / s;
}

// ---------------- launch ----------------
extern "C" void kernel_launch(void* const* d_in, const int* in_sizes, int n_in,
                              void* d_out, int out_size)
{
    const float* x   = (const float*)d_in[0];
    const int*   ei  = (const int*)d_in[1];
    const float* ew  = (const float*)d_in[2];
    const float* Wp  = (const float*)d_in[3];
    const float* bp  = (const float*)d_in[4];
    const float* W1  = (const float*)d_in[5];
    const float* b1  = (const float*)d_in[6];
    const float* W2  = (const float*)d_in[7];
    const float* b2  = (const float*)d_in[8];
    const float* Wl1 = (const float*)d_in[9];
    const float* bl1 = (const float*)d_in[10];
    const float* Wl2 = (const float*)d_in[11];
    const float* bl2 = (const float*)d_in[12];
    float* out = (float*)d_out;

    const int M = in_sizes[0] / 256;   // 100000
    const int E = in_sizes[1] / 2;     // 1600000
    const int* src = ei;
    const int* dst = ei + E;

    float *p_h, *p_t, *p_deg, *p_dinv, *p_ecoef;
    int *p_cnt, *p_off, *p_cur, *p_esrc, *p_part;
    cudaGetSymbolAddress((void**)&p_h, g_h);
    cudaGetSymbolAddress((void**)&p_t, g_t);
    cudaGetSymbolAddress((void**)&p_deg, g_deg);
    cudaGetSymbolAddress((void**)&p_dinv, g_dinv);
    cudaGetSymbolAddress((void**)&p_cnt, g_cnt);
    cudaGetSymbolAddress((void**)&p_off, g_off);
    cudaGetSymbolAddress((void**)&p_cur, g_cur);
    cudaGetSymbolAddress((void**)&p_esrc, g_esrc);
    cudaGetSymbolAddress((void**)&p_ecoef, g_ecoef);
    cudaGetSymbolAddress((void**)&p_part, g_part);

    const int gemm_blocks = (M + 127) / 128;
    const int agg_blocks  = (M + 7) / 8;
    const int scan_blocks = (M + SCAN_CHUNK - 1) / SCAN_CHUNK;

    // CSR build + normalization (reused by both conv layers)
    k_init<<<(M + 255) / 256, 256>>>(p_deg, p_cnt, M);
    k_edge_deg<<<(E + 255) / 256, 256>>>(dst, ew, p_deg, p_cnt, E);
    k_dinv<<<(M + 255) / 256, 256>>>(p_deg, p_dinv, M);
    k_scan1<<<scan_blocks, SCAN_CHUNK>>>(p_cnt, p_part, M);
    k_scan2<<<1, 512>>>(p_part, scan_blocks);
    k_scan3<<<scan_blocks, SCAN_CHUNK>>>(p_cnt, p_part, p_off, p_cur, M, E);
    k_scatter<<<(E + 255) / 256, 256>>>(src, dst, ew, p_dinv, p_cur, p_esrc, p_ecoef, E);

    // h0 = relu(x @ Wp + bp)
    k_gemm<256, 0><<<gemm_blocks, 256>>>(x, Wp, bp, p_h, M);

    // conv1: t = h0 @ W1; h = relu(aggregate(t) + b1)
    k_gemm<128, 1><<<gemm_blocks, 256>>>(p_h, W1, nullptr, p_t, M);
    k_agg<<<agg_blocks, 256>>>(p_off, p_esrc, p_ecoef, p_t, p_dinv, b1, p_h, M);

    // conv2
    k_gemm<128, 1><<<gemm_blocks, 256>>>(p_h, W2, nullptr, p_t, M);
    k_agg<<<agg_blocks, 256>>>(p_off, p_esrc, p_ecoef, p_t, p_dinv, b2, p_h, M);

    // h = relu(h @ Wl1 + bl1)
    k_gemm<128, 0><<<gemm_blocks, 256>>>(p_h, Wl1, bl1, p_t, M);

    // softmax(h @ Wl2 + bl2)
    k_logits_softmax<<<(M + 7) / 8, 256>>>(p_t, Wl2, bl2, out, M);
}

// round 4
// speedup vs baseline: 2.1195x; 1.0824x over previous
#include <cuda_runtime.h>
#include <math.h>

#define NN 100000
#define EE 1600000
#define CH 128
#define SCAN_CHUNK 256

// Scratch (no device allocation allowed)
__device__ float g_h[(size_t)NN * CH];
__device__ float g_t[(size_t)NN * CH];
__device__ float g_deg[NN];
__device__ float g_dinv[NN];
__device__ int   g_cnt[NN];
__device__ int   g_off[NN + 1];
__device__ int   g_cur[NN];
__device__ int   g_esrc[EE];
__device__ float g_ecoef[EE];
__device__ int   g_part[512];

// ---------------- init: deg=1 (self loop), cnt=0 ----------------
__global__ void k_init(float* deg, int* cnt, int n) {
    int i = blockIdx.x * blockDim.x + threadIdx.x;
    if (i < n) { deg[i] = 1.0f; cnt[i] = 0; }
}

__global__ void k_edge_deg(const int* __restrict__ dst, const float* __restrict__ ew,
                           float* deg, int* cnt, int E) {
    int e = blockIdx.x * blockDim.x + threadIdx.x;
    if (e < E) {
        int d = dst[e];
        atomicAdd(&deg[d], ew[e]);
        atomicAdd(&cnt[d], 1);
    }
}

__global__ void k_dinv(const float* __restrict__ deg, float* dinv, int n) {
    int i = blockIdx.x * blockDim.x + threadIdx.x;
    if (i < n) dinv[i] = rsqrtf(deg[i]);
}

// ---------------- parallel scan ----------------
__global__ __launch_bounds__(SCAN_CHUNK) void k_scan1(const int* __restrict__ cnt,
                                                      int* part, int n) {
    __shared__ int ws[8];
    int i = blockIdx.x * SCAN_CHUNK + threadIdx.x;
    int v = (i < n) ? cnt[i] : 0;
#pragma unroll
    for (int o = 16; o >= 1; o >>= 1) v += __shfl_xor_sync(0xFFFFFFFFu, v, o);
    if ((threadIdx.x & 31) == 0) ws[threadIdx.x >> 5] = v;
    __syncthreads();
    if (threadIdx.x == 0) {
        int s = 0;
#pragma unroll
        for (int w = 0; w < 8; w++) s += ws[w];
        part[blockIdx.x] = s;
    }
}

__global__ __launch_bounds__(512) void k_scan2(int* part, int nb) {
    __shared__ int s[512];
    int tid = threadIdx.x;
    int v = (tid < nb) ? part[tid] : 0;
    s[tid] = v;
    __syncthreads();
#pragma unroll
    for (int d = 1; d < 512; d <<= 1) {
        int add = (tid >= d) ? s[tid - d] : 0;
        __syncthreads();
        s[tid] += add;
        __syncthreads();
    }
    if (tid < nb) part[tid] = s[tid] - v;
}

__global__ __launch_bounds__(SCAN_CHUNK) void k_scan3(const int* __restrict__ cnt,
                                                      const int* __restrict__ part,
                                                      int* off, int* cur, int n, int E) {
    __shared__ int ws[8];
    int tid = threadIdx.x;
    int i = blockIdx.x * SCAN_CHUNK + tid;
    int lane = tid & 31;
    int warp = tid >> 5;
    int v = (i < n) ? cnt[i] : 0;
    int x = v;
#pragma unroll
    for (int o = 1; o < 32; o <<= 1) {
        int y = __shfl_up_sync(0xFFFFFFFFu, x, o);
        if (lane >= o) x += y;
    }
    if (lane == 31) ws[warp] = x;
    __syncthreads();
    if (warp == 0 && lane < 8) {
        int y = ws[lane];
        int z = y;
#pragma unroll
        for (int o = 1; o < 8; o <<= 1) {
            int u = __shfl_up_sync(0xFFu, z, o);
            if (lane >= o) z += u;
        }
        ws[lane] = z - y;
    }
    __syncthreads();
    if (i < n) {
        int excl = part[blockIdx.x] + ws[warp] + x - v;
        off[i] = excl;
        cur[i] = excl;
    }
    if (i == n - 1) off[n] = E;
}

__global__ void k_scatter(const int* __restrict__ src, const int* __restrict__ dst,
                          const float* __restrict__ ew, const float* __restrict__ dinv,
                          int* cur, int* esrc, float* ecoef, int E) {
    int e = blockIdx.x * blockDim.x + threadIdx.x;
    if (e >= E) return;
    int s = src[e];
    int d = dst[e];
    int pos = atomicAdd(&cur[d], 1);
    esrc[pos]  = s;
    ecoef[pos] = __ldg(dinv + s) * ew[e] * __ldg(dinv + d);
}

// ---------------- GEMM: [M,K] @ [K,128], BM=64 BN=128 BK=16, 128 thr, 8x8 micro ----------------
// double-buffered smem; EPI==0: out = relu(acc + bias);  EPI==1: out = acc
template <int K, int EPI>
__global__ __launch_bounds__(128) void k_gemm(
    const float* __restrict__ A, const float* __restrict__ W,
    const float* __restrict__ bias, float* __restrict__ out, int M)
{
    __shared__ float As[2][16][64];
    __shared__ float Ws[2][16][128];

    const int tid = threadIdx.x;
    const int tx = (tid & 15) * 8;   // col 0..120
    const int ty = (tid >> 4) * 8;   // row 0..56
    const int row0 = blockIdx.x * 64;

    float acc[8][8];
#pragma unroll
    for (int i = 0; i < 8; i++)
#pragma unroll
        for (int j = 0; j < 8; j++) acc[i][j] = 0.0f;

    // A load map: 256 float4 per tile, 2 per thread
    const int ar0 = tid >> 2;               // rows 0..31
    const int ar1 = ar0 + 32;               // rows 32..63
    const int akc = (tid & 3) * 4;          // k offset 0,4,8,12
    // W load map: 512 float4, 4 per thread
    const int wr0 = tid >> 5;               // base k row 0..3 (stride 4)
    const int wc  = (tid & 31) * 4;         // col 0..124

    float4 a0, a1, w0, w1, w2, w3;

    // prefetch first tile
    {
        int g0 = row0 + ar0, g1 = row0 + ar1;
        a0 = (g0 < M) ? *(const float4*)&A[(size_t)g0 * K + akc] : make_float4(0,0,0,0);
        a1 = (g1 < M) ? *(const float4*)&A[(size_t)g1 * K + akc] : make_float4(0,0,0,0);
        w0 = *(const float4*)&W[(size_t)(wr0 +  0) * 128 + wc];
        w1 = *(const float4*)&W[(size_t)(wr0 +  4) * 128 + wc];
        w2 = *(const float4*)&W[(size_t)(wr0 +  8) * 128 + wc];
        w3 = *(const float4*)&W[(size_t)(wr0 + 12) * 128 + wc];
    }

    int buf = 0;
#pragma unroll 1
    for (int k0 = 0; k0 < K; k0 += 16) {
        // store prefetched tile to smem[buf]
        As[buf][akc + 0][ar0] = a0.x;
        As[buf][akc + 1][ar0] = a0.y;
        As[buf][akc + 2][ar0] = a0.z;
        As[buf][akc + 3][ar0] = a0.w;
        As[buf][akc + 0][ar1] = a1.x;
        As[buf][akc + 1][ar1] = a1.y;
        As[buf][akc + 2][ar1] = a1.z;
        As[buf][akc + 3][ar1] = a1.w;
        *(float4*)&Ws[buf][wr0 +  0][wc] = w0;
        *(float4*)&Ws[buf][wr0 +  4][wc] = w1;
        *(float4*)&Ws[buf][wr0 +  8][wc] = w2;
        *(float4*)&Ws[buf][wr0 + 12][wc] = w3;
        __syncthreads();

        // prefetch next tile into registers (overlaps with compute below)
        if (k0 + 16 < K) {
            int kn = k0 + 16;
            int g0 = row0 + ar0, g1 = row0 + ar1;
            a0 = (g0 < M) ? *(const float4*)&A[(size_t)g0 * K + kn + akc] : make_float4(0,0,0,0);
            a1 = (g1 < M) ? *(const float4*)&A[(size_t)g1 * K + kn + akc] : make_float4(0,0,0,0);
            w0 = *(const float4*)&W[(size_t)(kn + wr0 +  0) * 128 + wc];
            w1 = *(const float4*)&W[(size_t)(kn + wr0 +  4) * 128 + wc];
            w2 = *(const float4*)&W[(size_t)(kn + wr0 +  8) * 128 + wc];
            w3 = *(const float4*)&W[(size_t)(kn + wr0 + 12) * 128 + wc];
        }

#pragma unroll
        for (int kk = 0; kk < 16; kk++) {
            float a[8], b[8];
            *(float4*)&a[0] = *(float4*)&As[buf][kk][ty];
            *(float4*)&a[4] = *(float4*)&As[buf][kk][ty + 4];
            *(float4*)&b[0] = *(float4*)&Ws[buf][kk][tx];
            *(float4*)&b[4] = *(float4*)&Ws[buf][kk][tx + 4];
#pragma unroll
            for (int i = 0; i < 8; i++)
#pragma unroll
                for (int j = 0; j < 8; j++)
                    acc[i][j] += a[i] * b[j];
        }
        buf ^= 1;
        if (k0 + 16 < K) __syncthreads();
    }

    float bv[8];
    if (EPI == 0) {
        *(float4*)&bv[0] = *(const float4*)&bias[tx];
        *(float4*)&bv[4] = *(const float4*)&bias[tx + 4];
    }
#pragma unroll
    for (int i = 0; i < 8; i++) {
        int r = row0 + ty + i;
        if (r >= M) break;
        float o[8];
#pragma unroll
        for (int j = 0; j < 8; j++) {
            o[j] = acc[i][j];
            if (EPI == 0) o[j] = fmaxf(o[j] + bv[j], 0.f);
        }
        *(float4*)&out[(size_t)r * 128 + tx]     = *(float4*)&o[0];
        *(float4*)&out[(size_t)r * 128 + tx + 4] = *(float4*)&o[4];
    }
}

// ---------------- gather aggregation: one warp per node ----------------
__global__ __launch_bounds__(256) void k_agg(
    const int* __restrict__ off, const int* __restrict__ esrc,
    const float* __restrict__ ecoef, const float* __restrict__ t,
    const float* __restrict__ dinv, const float* __restrict__ bias,
    float* __restrict__ out, int n)
{
    int w = (blockIdx.x * blockDim.x + threadIdx.x) >> 5;
    if (w >= n) return;
    int lane = threadIdx.x & 31;

    const float4* tp = (const float4*)t;
    int beg = __ldg(off + w);
    int end = __ldg(off + w + 1);

    float di = __ldg(dinv + w);
    float s = di * di;
    float4 acc = tp[(size_t)w * 32 + lane];
    acc.x *= s; acc.y *= s; acc.z *= s; acc.w *= s;

    int e = beg;
    for (; e + 1 < end; e += 2) {
        int s0 = __ldg(esrc + e);
        int s1 = __ldg(esrc + e + 1);
        float c0 = __ldg(ecoef + e);
        float c1 = __ldg(ecoef + e + 1);
        float4 h0 = tp[(size_t)s0 * 32 + lane];
        float4 h1 = tp[(size_t)s1 * 32 + lane];
        acc.x += c0 * h0.x + c1 * h1.x;
        acc.y += c0 * h0.y + c1 * h1.y;
        acc.z += c0 * h0.z + c1 * h1.z;
        acc.w += c0 * h0.w + c1 * h1.w;
    }
    if (e < end) {
        int s0 = __ldg(esrc + e);
        float c0 = __ldg(ecoef + e);
        float4 h0 = tp[(size_t)s0 * 32 + lane];
        acc.x += c0 * h0.x;
        acc.y += c0 * h0.y;
        acc.z += c0 * h0.z;
        acc.w += c0 * h0.w;
    }

    float4 bv = *(const float4*)&bias[lane * 4];
    acc.x = fmaxf(acc.x + bv.x, 0.f);
    acc.y = fmaxf(acc.y + bv.y, 0.f);
    acc.z = fmaxf(acc.z + bv.z, 0.f);
    acc.w = fmaxf(acc.w + bv.w, 0.f);
    ((float4*)out)[(size_t)w * 32 + lane] = acc;
}

// ---------------- logits + softmax ----------------
__global__ __launch_bounds__(256) void k_logits_softmax(
    const float* __restrict__ h, const float* __restrict__ Wl2,
    const float* __restrict__ bl2, float* __restrict__ out, int M)
{
    __shared__ float hs[8][128];
    int tid = threadIdx.x;
    int warp = tid >> 5;
    int lane = tid & 31;
    int row0 = blockIdx.x * 8;

    {
        int rloc = tid >> 5;
        int cloc = (tid & 31) * 4;
        int r = row0 + rloc;
        float4 v = make_float4(0.f, 0.f, 0.f, 0.f);
        if (r < M) v = *(const float4*)&h[(size_t)r * 128 + cloc];
        *(float4*)&hs[rloc][cloc] = v;
    }
    __syncthreads();

    int r = row0 + warp;
    if (r >= M) return;

    float acc = bl2[lane];
#pragma unroll
    for (int k = 0; k < 128; k++) {
        acc += hs[warp][k] * __ldg(&Wl2[(size_t)k * 32 + lane]);
    }

    float m = acc;
#pragma unroll
    for (int o = 16; o >= 1; o >>= 1) m = fmaxf(m, __shfl_xor_sync(0xFFFFFFFFu, m, o));
    float e = __expf(acc - m);
    float s = e;
#pragma unroll
    for (int o = 16; o >= 1; o >>= 1) s += __shfl_xor_sync(0xFFFFFFFFu, s, o);
    out[(size_t)r * 32 + lane] = e / s;
}

// ---------------- launch ----------------
extern "C" void kernel_launch(void* const* d_in, const int* in_sizes, int n_in,
                              void* d_out, int out_size)
{
    const float* x   = (const float*)d_in[0];
    const int*   ei  = (const int*)d_in[1];
    const float* ew  = (const float*)d_in[2];
    const float* Wp  = (const float*)d_in[3];
    const float* bp  = (const float*)d_in[4];
    const float* W1  = (const float*)d_in[5];
    const float* b1  = (const float*)d_in[6];
    const float* W2  = (const float*)d_in[7];
    const float* b2  = (const float*)d_in[8];
    const float* Wl1 = (const float*)d_in[9];
    const float* bl1 = (const float*)d_in[10];
    const float* Wl2 = (const float*)d_in[11];
    const float* bl2 = (const float*)d_in[12];
    float* out = (float*)d_out;

    const int M = in_sizes[0] / 256;   // 100000
    const int E = in_sizes[1] / 2;     // 1600000
    const int* src = ei;
    const int* dst = ei + E;

    float *p_h, *p_t, *p_deg, *p_dinv, *p_ecoef;
    int *p_cnt, *p_off, *p_cur, *p_esrc, *p_part;
    cudaGetSymbolAddress((void**)&p_h, g_h);
    cudaGetSymbolAddress((void**)&p_t, g_t);
    cudaGetSymbolAddress((void**)&p_deg, g_deg);
    cudaGetSymbolAddress((void**)&p_dinv, g_dinv);
    cudaGetSymbolAddress((void**)&p_cnt, g_cnt);
    cudaGetSymbolAddress((void**)&p_off, g_off);
    cudaGetSymbolAddress((void**)&p_cur, g_cur);
    cudaGetSymbolAddress((void**)&p_esrc, g_esrc);
    cudaGetSymbolAddress((void**)&p_ecoef, g_ecoef);
    cudaGetSymbolAddress((void**)&p_part, g_part);

    const int gemm_blocks = (M + 63) / 64;
    const int agg_blocks  = (M + 7) / 8;
    const int scan_blocks = (M + SCAN_CHUNK - 1) / SCAN_CHUNK;

    // CSR build + normalization (reused by both conv layers)
    k_init<<<(M + 255) / 256, 256>>>(p_deg, p_cnt, M);
    k_edge_deg<<<(E + 255) / 256, 256>>>(dst, ew, p_deg, p_cnt, E);
    k_dinv<<<(M + 255) / 256, 256>>>(p_deg, p_dinv, M);
    k_scan1<<<scan_blocks, SCAN_CHUNK>>>(p_cnt, p_part, M);
    k_scan2<<<1, 512>>>(p_part, scan_blocks);
    k_scan3<<<scan_blocks, SCAN_CHUNK>>>(p_cnt, p_part, p_off, p_cur, M, E);
    k_scatter<<<(E + 255) / 256, 256>>>(src, dst, ew, p_dinv, p_cur, p_esrc, p_ecoef, E);

    // h0 = relu(x @ Wp + bp)
    k_gemm<256, 0><<<gemm_blocks, 128>>>(x, Wp, bp, p_h, M);

    // conv1: t = h0 @ W1; h = relu(aggregate(t) + b1)
    k_gemm<128, 1><<<gemm_blocks, 128>>>(p_h, W1, nullptr, p_t, M);
    k_agg<<<agg_blocks, 256>>>(p_off, p_esrc, p_ecoef, p_t, p_dinv, b1, p_h, M);

    // conv2
    k_gemm<128, 1><<<gemm_blocks, 128>>>(p_h, W2, nullptr, p_t, M);
    k_agg<<<agg_blocks, 256>>>(p_off, p_esrc, p_ecoef, p_t, p_dinv, b2, p_h, M);

    // h = relu(h @ Wl1 + bl1)
    k_gemm<128, 0><<<gemm_blocks, 128>>>(p_h, Wl1, bl1, p_t, M);

    // softmax(h @ Wl2 + bl2)
    k_logits_softmax<<<(M + 7) / 8, 256>>>(p_t, Wl2, bl2, out, M);
}

// round 6
// speedup vs baseline: 2.3763x; 1.1212x over previous
#include <cuda_runtime.h>
#include <cuda_bf16.h>
#include <math.h>
#include <stdint.h>

#define NN 100000
#define EE 1600000
#define SCAN_CHUNK 256

// Scratch (no device allocation allowed)
__device__ float g_h[(size_t)NN * 128];
__device__ float g_t[(size_t)NN * 128];
__device__ float g_deg[NN];
__device__ float g_dinv[NN];
__device__ int   g_cnt[NN];
__device__ int   g_off[NN + 1];
__device__ int   g_cur[NN];
__device__ int   g_esrc[EE];
__device__ float g_ecoef[EE];
__device__ int   g_part[512];
// transposed + split weights: Wp^T @0 (128x256), W1^T @32768, W2^T @49152, Wl1^T @65536
__device__ __nv_bfloat16 g_whi[81920];
__device__ __nv_bfloat16 g_wlo[81920];

// ================= mma.sync helpers (baseline PTX, sm_80+) =================
__device__ __forceinline__ void ldsm4(uint32_t d[4], const void* p) {
    uint32_t a = (uint32_t)__cvta_generic_to_shared(p);
    asm volatile("ldmatrix.sync.aligned.m8n8.x4.shared.b16 {%0,%1,%2,%3}, [%4];"
        : "=r"(d[0]), "=r"(d[1]), "=r"(d[2]), "=r"(d[3]) : "r"(a));
}
__device__ __forceinline__ void ldsm2(uint32_t d[2], const void* p) {
    uint32_t a = (uint32_t)__cvta_generic_to_shared(p);
    asm volatile("ldmatrix.sync.aligned.m8n8.x2.shared.b16 {%0,%1}, [%2];"
        : "=r"(d[0]), "=r"(d[1]) : "r"(a));
}
__device__ __forceinline__ void mma16816(float c[4], const uint32_t a[4], const uint32_t b[2]) {
    asm volatile("mma.sync.aligned.m16n8k16.row.col.f32.bf16.bf16.f32 "
        "{%0,%1,%2,%3}, {%4,%5,%6,%7}, {%8,%9}, {%0,%1,%2,%3};"
        : "+f"(c[0]), "+f"(c[1]), "+f"(c[2]), "+f"(c[3])
        : "r"(a[0]), "r"(a[1]), "r"(a[2]), "r"(a[3]), "r"(b[0]), "r"(b[1]));
}
__device__ __forceinline__ uint32_t pack_bf16(__nv_bfloat16 a, __nv_bfloat16 b) {
    return (uint32_t)__bfloat16_as_ushort(a) | ((uint32_t)__bfloat16_as_ushort(b) << 16);
}

// ================= CSR build =================
__global__ void k_init(float* deg, int* cnt, int n) {
    int i = blockIdx.x * blockDim.x + threadIdx.x;
    if (i < n) { deg[i] = 1.0f; cnt[i] = 0; }
}
__global__ void k_edge_deg(const int* __restrict__ dst, const float* __restrict__ ew,
                           float* deg, int* cnt, int E) {
    int e = blockIdx.x * blockDim.x + threadIdx.x;
    if (e < E) {
        int d = dst[e];
        atomicAdd(&deg[d], ew[e]);
        atomicAdd(&cnt[d], 1);
    }
}
__global__ void k_dinv(const float* __restrict__ deg, float* dinv, int n) {
    int i = blockIdx.x * blockDim.x + threadIdx.x;
    if (i < n) dinv[i] = rsqrtf(deg[i]);
}
__global__ __launch_bounds__(SCAN_CHUNK) void k_scan1(const int* __restrict__ cnt,
                                                      int* part, int n) {
    __shared__ int ws[8];
    int i = blockIdx.x * SCAN_CHUNK + threadIdx.x;
    int v = (i < n) ? cnt[i] : 0;
#pragma unroll
    for (int o = 16; o >= 1; o >>= 1) v += __shfl_xor_sync(0xFFFFFFFFu, v, o);
    if ((threadIdx.x & 31) == 0) ws[threadIdx.x >> 5] = v;
    __syncthreads();
    if (threadIdx.x == 0) {
        int s = 0;
#pragma unroll
        for (int w = 0; w < 8; w++) s += ws[w];
        part[blockIdx.x] = s;
    }
}
__global__ __launch_bounds__(512) void k_scan2(int* part, int nb) {
    __shared__ int s[512];
    int tid = threadIdx.x;
    int v = (tid < nb) ? part[tid] : 0;
    s[tid] = v;
    __syncthreads();
#pragma unroll
    for (int d = 1; d < 512; d <<= 1) {
        int add = (tid >= d) ? s[tid - d] : 0;
        __syncthreads();
        s[tid] += add;
        __syncthreads();
    }
    if (tid < nb) part[tid] = s[tid] - v;
}
__global__ __launch_bounds__(SCAN_CHUNK) void k_scan3(const int* __restrict__ cnt,
                                                      const int* __restrict__ part,
                                                      int* off, int* cur, int n, int E) {
    __shared__ int ws[8];
    int tid = threadIdx.x;
    int i = blockIdx.x * SCAN_CHUNK + tid;
    int lane = tid & 31;
    int warp = tid >> 5;
    int v = (i < n) ? cnt[i] : 0;
    int x = v;
#pragma unroll
    for (int o = 1; o < 32; o <<= 1) {
        int y = __shfl_up_sync(0xFFFFFFFFu, x, o);
        if (lane >= o) x += y;
    }
    if (lane == 31) ws[warp] = x;
    __syncthreads();
    if (warp == 0 && lane < 8) {
        int y = ws[lane];
        int z = y;
#pragma unroll
        for (int o = 1; o < 8; o <<= 1) {
            int u = __shfl_up_sync(0xFFu, z, o);
            if (lane >= o) z += u;
        }
        ws[lane] = z - y;
    }
    __syncthreads();
    if (i < n) {
        int excl = part[blockIdx.x] + ws[warp] + x - v;
        off[i] = excl;
        cur[i] = excl;
    }
    if (i == n - 1) off[n] = E;
}
__global__ void k_scatter(const int* __restrict__ src, const int* __restrict__ dst,
                          const float* __restrict__ ew, const float* __restrict__ dinv,
                          int* cur, int* esrc, float* ecoef, int E) {
    int e = blockIdx.x * blockDim.x + threadIdx.x;
    if (e >= E) return;
    int s = src[e];
    int d = dst[e];
    int pos = atomicAdd(&cur[d], 1);
    esrc[pos]  = s;
    ecoef[pos] = __ldg(dinv + s) * ew[e] * __ldg(dinv + d);
}

// ================= weight transpose + bf16 split =================
__global__ void k_prep_w(const float* __restrict__ W, int K, int N,
                         __nv_bfloat16* hi, __nv_bfloat16* lo) {
    int idx = blockIdx.x * blockDim.x + threadIdx.x;
    if (idx >= K * N) return;
    int n = idx / K, k = idx % K;
    float w = W[(size_t)k * N + n];
    __nv_bfloat16 h = __float2bfloat16(w);
    hi[idx] = h;
    lo[idx] = __float2bfloat16(w - __bfloat162float(h));
}

// ================= HMMA GEMM: out[M,128] = A[M,K] @ W[K,128] =================
// split-bf16 (hi/lo), mma.sync m16n8k16, BM=64 BN=128 BK=64, 128 threads.
// EPI==0: out = relu(acc + bias);  EPI==1: out = acc
#define KP 72
#define SM_AH 0
#define SM_AL (64 * KP * 2)
#define SM_BH (2 * 64 * KP * 2)
#define SM_BL (SM_BH + 128 * KP * 2)
#define GEMM_SMEM (SM_BL + 128 * KP * 2)   // 55296 bytes

template <int K, int EPI>
__global__ __launch_bounds__(128) void k_gemm_mma(
    const float* __restrict__ A, const __nv_bfloat16* __restrict__ Whi,
    const __nv_bfloat16* __restrict__ Wlo, const float* __restrict__ bias,
    float* __restrict__ out, int M)
{
    extern __shared__ char sm[];
    __nv_bfloat16* Ah = (__nv_bfloat16*)(sm + SM_AH);
    __nv_bfloat16* Al = (__nv_bfloat16*)(sm + SM_AL);
    __nv_bfloat16* Bh = (__nv_bfloat16*)(sm + SM_BH);
    __nv_bfloat16* Bl = (__nv_bfloat16*)(sm + SM_BL);

    const int tid  = threadIdx.x;
    const int wid  = tid >> 5;
    const int lane = tid & 31;
    const int wm   = wid & 1;       // warp row: 32 output rows
    const int wn   = wid >> 1;      // warp col: 64 output cols
    const int row0 = blockIdx.x * 64;

    float acc[2][8][4];
#pragma unroll
    for (int mt = 0; mt < 2; mt++)
#pragma unroll
        for (int nt = 0; nt < 8; nt++)
#pragma unroll
            for (int j = 0; j < 4; j++) acc[mt][nt][j] = 0.0f;

#pragma unroll 1
    for (int kc = 0; kc < K; kc += 64) {
        if (kc) __syncthreads();
        // ---- A fill: row = tid>>1 (0..63), 8 float4 each, convert to hi/lo ----
        {
            int r = tid >> 1;
            int gr = row0 + r;
            int c0 = (tid & 1) * 8;   // float4 index base
            const float4* ap = (const float4*)(A + (size_t)gr * K + kc) + c0;
            __nv_bfloat16* dh = Ah + r * KP + c0 * 4;
            __nv_bfloat16* dl = Al + r * KP + c0 * 4;
            bool ok = gr < M;
#pragma unroll
            for (int j = 0; j < 8; j++) {
                float4 v = ok ? ap[j] : make_float4(0.f, 0.f, 0.f, 0.f);
                __nv_bfloat16 h0 = __float2bfloat16(v.x);
                __nv_bfloat16 h1 = __float2bfloat16(v.y);
                __nv_bfloat16 h2 = __float2bfloat16(v.z);
                __nv_bfloat16 h3 = __float2bfloat16(v.w);
                __nv_bfloat16 l0 = __float2bfloat16(v.x - __bfloat162float(h0));
                __nv_bfloat16 l1 = __float2bfloat16(v.y - __bfloat162float(h1));
                __nv_bfloat16 l2 = __float2bfloat16(v.z - __bfloat162float(h2));
                __nv_bfloat16 l3 = __float2bfloat16(v.w - __bfloat162float(h3));
                *(uint2*)(dh + j * 4) = make_uint2(pack_bf16(h0, h1), pack_bf16(h2, h3));
                *(uint2*)(dl + j * 4) = make_uint2(pack_bf16(l0, l1), pack_bf16(l2, l3));
            }
        }
        // ---- B fill: row n = tid (0..127), 8 uint4 hi + 8 uint4 lo ----
        {
            const uint4* bh = (const uint4*)(Whi + (size_t)tid * K + kc);
            const uint4* bl = (const uint4*)(Wlo + (size_t)tid * K + kc);
            uint4* dh = (uint4*)(Bh + tid * KP);
            uint4* dl = (uint4*)(Bl + tid * KP);
#pragma unroll
            for (int j = 0; j < 8; j++) { dh[j] = bh[j]; dl[j] = bl[j]; }
        }
        __syncthreads();

#pragma unroll
        for (int ks = 0; ks < 64; ks += 16) {
            uint32_t ah[2][4], al[2][4], bhf[8][2], blf[8][2];
#pragma unroll
            for (int mt = 0; mt < 2; mt++) {
                int r = wm * 32 + mt * 16 + (lane & 15);
                int c = ks + ((lane >> 4) << 3);
                ldsm4(ah[mt], Ah + r * KP + c);
                ldsm4(al[mt], Al + r * KP + c);
            }
#pragma unroll
            for (int nt = 0; nt < 8; nt++) {
                int n = wn * 64 + nt * 8 + (lane & 7);
                int c = ks + ((lane >> 3) & 1) * 8;
                ldsm2(bhf[nt], Bh + n * KP + c);
                ldsm2(blf[nt], Bl + n * KP + c);
            }
#pragma unroll
            for (int mt = 0; mt < 2; mt++)
#pragma unroll
                for (int nt = 0; nt < 8; nt++) {
                    mma16816(acc[mt][nt], ah[mt], bhf[nt]);
                    mma16816(acc[mt][nt], ah[mt], blf[nt]);
                    mma16816(acc[mt][nt], al[mt], bhf[nt]);
                }
        }
    }

    // ---- epilogue ----
#pragma unroll
    for (int mt = 0; mt < 2; mt++) {
        int r1 = row0 + wm * 32 + mt * 16 + (lane >> 2);
        int r2 = r1 + 8;
#pragma unroll
        for (int nt = 0; nt < 8; nt++) {
            int c = wn * 64 + nt * 8 + (lane & 3) * 2;
            float2 v1 = make_float2(acc[mt][nt][0], acc[mt][nt][1]);
            float2 v2 = make_float2(acc[mt][nt][2], acc[mt][nt][3]);
            if (EPI == 0) {
                float b0 = __ldg(bias + c), b1 = __ldg(bias + c + 1);
                v1.x = fmaxf(v1.x + b0, 0.f); v1.y = fmaxf(v1.y + b1, 0.f);
                v2.x = fmaxf(v2.x + b0, 0.f); v2.y = fmaxf(v2.y + b1, 0.f);
            }
            if (r1 < M) *(float2*)&out[(size_t)r1 * 128 + c] = v1;
            if (r2 < M) *(float2*)&out[(size_t)r2 * 128 + c] = v2;
        }
    }
}

// ================= gather aggregation: one warp per node =================
__global__ __launch_bounds__(256) void k_agg(
    const int* __restrict__ off, const int* __restrict__ esrc,
    const float* __restrict__ ecoef, const float* __restrict__ t,
    const float* __restrict__ dinv, const float* __restrict__ bias,
    float* __restrict__ out, int n)
{
    int w = (blockIdx.x * blockDim.x + threadIdx.x) >> 5;
    if (w >= n) return;
    int lane = threadIdx.x & 31;

    const float4* tp = (const float4*)t;
    int beg = __ldg(off + w);
    int end = __ldg(off + w + 1);

    float di = __ldg(dinv + w);
    float s = di * di;
    float4 acc = tp[(size_t)w * 32 + lane];
    acc.x *= s; acc.y *= s; acc.z *= s; acc.w *= s;

    int e = beg;
    for (; e + 1 < end; e += 2) {
        int s0 = __ldg(esrc + e);
        int s1 = __ldg(esrc + e + 1);
        float c0 = __ldg(ecoef + e);
        float c1 = __ldg(ecoef + e + 1);
        float4 h0 = tp[(size_t)s0 * 32 + lane];
        float4 h1 = tp[(size_t)s1 * 32 + lane];
        acc.x += c0 * h0.x + c1 * h1.x;
        acc.y += c0 * h0.y + c1 * h1.y;
        acc.z += c0 * h0.z + c1 * h1.z;
        acc.w += c0 * h0.w + c1 * h1.w;
    }
    if (e < end) {
        int s0 = __ldg(esrc + e);
        float c0 = __ldg(ecoef + e);
        float4 h0 = tp[(size_t)s0 * 32 + lane];
        acc.x += c0 * h0.x;
        acc.y += c0 * h0.y;
        acc.z += c0 * h0.z;
        acc.w += c0 * h0.w;
    }

    float4 bv = *(const float4*)&bias[lane * 4];
    acc.x = fmaxf(acc.x + bv.x, 0.f);
    acc.y = fmaxf(acc.y + bv.y, 0.f);
    acc.z = fmaxf(acc.z + bv.z, 0.f);
    acc.w = fmaxf(acc.w + bv.w, 0.f);
    ((float4*)out)[(size_t)w * 32 + lane] = acc;
}

// ================= logits + softmax =================
__global__ __launch_bounds__(256) void k_logits_softmax(
    const float* __restrict__ h, const float* __restrict__ Wl2,
    const float* __restrict__ bl2, float* __restrict__ out, int M)
{
    __shared__ float hs[8][128];
    int tid = threadIdx.x;
    int warp = tid >> 5;
    int lane = tid & 31;
    int row0 = blockIdx.x * 8;

    {
        int rloc = tid >> 5;
        int cloc = (tid & 31) * 4;
        int r = row0 + rloc;
        float4 v = make_float4(0.f, 0.f, 0.f, 0.f);
        if (r < M) v = *(const float4*)&h[(size_t)r * 128 + cloc];
        *(float4*)&hs[rloc][cloc] = v;
    }
    __syncthreads();

    int r = row0 + warp;
    if (r >= M) return;

    float acc = bl2[lane];
#pragma unroll
    for (int k = 0; k < 128; k++) {
        acc += hs[warp][k] * __ldg(&Wl2[(size_t)k * 32 + lane]);
    }

    float m = acc;
#pragma unroll
    for (int o = 16; o >= 1; o >>= 1) m = fmaxf(m, __shfl_xor_sync(0xFFFFFFFFu, m, o));
    float e = __expf(acc - m);
    float s = e;
#pragma unroll
    for (int o = 16; o >= 1; o >>= 1) s += __shfl_xor_sync(0xFFFFFFFFu, s, o);
    out[(size_t)r * 32 + lane] = e / s;
}

// ================= launch =================
extern "C" void kernel_launch(void* const* d_in, const int* in_sizes, int n_in,
                              void* d_out, int out_size)
{
    const float* x   = (const float*)d_in[0];
    const int*   ei  = (const int*)d_in[1];
    const float* ew  = (const float*)d_in[2];
    const float* Wp  = (const float*)d_in[3];
    const float* bp  = (const float*)d_in[4];
    const float* W1  = (const float*)d_in[5];
    const float* b1  = (const float*)d_in[6];
    const float* W2  = (const float*)d_in[7];
    const float* b2  = (const float*)d_in[8];
    const float* Wl1 = (const float*)d_in[9];
    const float* bl1 = (const float*)d_in[10];
    const float* Wl2 = (const float*)d_in[11];
    const float* bl2 = (const float*)d_in[12];
    float* out = (float*)d_out;

    const int M = in_sizes[0] / 256;   // 100000
    const int E = in_sizes[1] / 2;     // 1600000
    const int* src = ei;
    const int* dst = ei + E;

    float *p_h, *p_t, *p_deg, *p_dinv, *p_ecoef;
    int *p_cnt, *p_off, *p_cur, *p_esrc, *p_part;
    __nv_bfloat16 *p_whi, *p_wlo;
    cudaGetSymbolAddress((void**)&p_h, g_h);
    cudaGetSymbolAddress((void**)&p_t, g_t);
    cudaGetSymbolAddress((void**)&p_deg, g_deg);
    cudaGetSymbolAddress((void**)&p_dinv, g_dinv);
    cudaGetSymbolAddress((void**)&p_cnt, g_cnt);
    cudaGetSymbolAddress((void**)&p_off, g_off);
    cudaGetSymbolAddress((void**)&p_cur, g_cur);
    cudaGetSymbolAddress((void**)&p_esrc, g_esrc);
    cudaGetSymbolAddress((void**)&p_ecoef, g_ecoef);
    cudaGetSymbolAddress((void**)&p_part, g_part);
    cudaGetSymbolAddress((void**)&p_whi, g_whi);
    cudaGetSymbolAddress((void**)&p_wlo, g_wlo);

    cudaFuncSetAttribute(k_gemm_mma<256, 0>, cudaFuncAttributeMaxDynamicSharedMemorySize, GEMM_SMEM);
    cudaFuncSetAttribute(k_gemm_mma<128, 1>, cudaFuncAttributeMaxDynamicSharedMemorySize, GEMM_SMEM);
    cudaFuncSetAttribute(k_gemm_mma<128, 0>, cudaFuncAttributeMaxDynamicSharedMemorySize, GEMM_SMEM);

    const int gemm_blocks = (M + 63) / 64;
    const int agg_blocks  = (M + 7) / 8;
    const int scan_blocks = (M + SCAN_CHUNK - 1) / SCAN_CHUNK;

    // weight transpose + split (tiny)
    k_prep_w<<<(256 * 128 + 255) / 256, 256>>>(Wp,  256, 128, p_whi,         p_wlo);
    k_prep_w<<<(128 * 128 + 255) / 256, 256>>>(W1,  128, 128, p_whi + 32768, p_wlo + 32768);
    k_prep_w<<<(128 * 128 + 255) / 256, 256>>>(W2,  128, 128, p_whi + 49152, p_wlo + 49152);
    k_prep_w<<<(128 * 128 + 255) / 256, 256>>>(Wl1, 128, 128, p_whi + 65536, p_wlo + 65536);

    // CSR build + normalization (reused by both conv layers)
    k_init<<<(M + 255) / 256, 256>>>(p_deg, p_cnt, M);
    k_edge_deg<<<(E + 255) / 256, 256>>>(dst, ew, p_deg, p_cnt, E);
    k_dinv<<<(M + 255) / 256, 256>>>(p_deg, p_dinv, M);
    k_scan1<<<scan_blocks, SCAN_CHUNK>>>(p_cnt, p_part, M);
    k_scan2<<<1, 512>>>(p_part, scan_blocks);
    k_scan3<<<scan_blocks, SCAN_CHUNK>>>(p_cnt, p_part, p_off, p_cur, M, E);
    k_scatter<<<(E + 255) / 256, 256>>>(src, dst, ew, p_dinv, p_cur, p_esrc, p_ecoef, E);

    // h0 = relu(x @ Wp + bp)
    k_gemm_mma<256, 0><<<gemm_blocks, 128, GEMM_SMEM>>>(x, p_whi, p_wlo, bp, p_h, M);

    // conv1: t = h0 @ W1; h = relu(aggregate(t) + b1)
    k_gemm_mma<128, 1><<<gemm_blocks, 128, GEMM_SMEM>>>(p_h, p_whi + 32768, p_wlo + 32768, nullptr, p_t, M);
    k_agg<<<agg_blocks, 256>>>(p_off, p_esrc, p_ecoef, p_t, p_dinv, b1, p_h, M);

    // conv2
    k_gemm_mma<128, 1><<<gemm_blocks, 128, GEMM_SMEM>>>(p_h, p_whi + 49152, p_wlo + 49152, nullptr, p_t, M);
    k_agg<<<agg_blocks, 256>>>(p_off, p_esrc, p_ecoef, p_t, p_dinv, b2, p_h, M);

    // h = relu(h @ Wl1 + bl1)
    k_gemm_mma<128, 0><<<gemm_blocks, 128, GEMM_SMEM>>>(p_h, p_whi + 65536, p_wlo + 65536, bl1, p_t, M);

    // softmax(h @ Wl2 + bl2)
    k_logits_softmax<<<(M + 7) / 8, 256>>>(p_t, Wl2, bl2, out, M);
}